// round 16
// baseline (speedup 1.0000x reference)
#include <cuda_runtime.h>
#include <cuda_bf16.h>
#include <cuda_fp16.h>
#include <cstdint>

#define BB 4
#define CC 64
#define HH 96
#define WW 96
#define TT 18
#define KK 9
#define OO 64
#define HWIMG (HH*WW)          // 9216
#define NPIX (BB*HWIMG)        // 36864
#define MT 128                 // pixels per tile
#define NTIL (NPIX/MT)         // 288

// -------- scratch (device globals) --------
__device__ uint2 g_xh16[NPIX * 16];                  // packed fp16, 8B per 4-ch chunk
__device__ uint4 g_wdc16[KK * 512];                  // fp16 swizzled [k][o:64][c:64], 8KB/tap
__device__ uint4 g_woff16[KK * 256];                 // fp16 swizzled [k][o:32][c:64], 4KB/tap

// ---------------- helpers ----------------
__device__ __forceinline__ uint32_t smem_u32(const void* p) {
    uint32_t a;
    asm("{ .reg .u64 t; cvta.to.shared.u64 t, %1; cvt.u32.u64 %0, t; }" : "=r"(a) : "l"(p));
    return a;
}
#define SWZ(b) ((b) ^ (((b) >> 3) & 0x70))

__device__ __forceinline__ uint32_t pack_f16(float a, float b) {
    __half2 t = __floats2half2_rn(a, b);
    return *(uint32_t*)&t;
}
__device__ __forceinline__ uint32_t splat_h2(float a) {
    __half2 t = __float2half2_rn(a);
    return *(uint32_t*)&t;
}
__device__ __forceinline__ __half2 u2h(uint32_t v) { return *(__half2*)&v; }
__device__ __forceinline__ uint32_t h2u(__half2 v) { return *(uint32_t*)&v; }

#define STS64(a, r0, r1) asm volatile("st.shared.v2.b32 [%0], {%1,%2};" :: "r"(a), "r"(r0), "r"(r1) : "memory")
#define CPA8(d, s, sz) asm volatile("cp.async.ca.shared.global [%0], [%1], 8, %2;" :: "r"(d), "l"(s), "r"(sz) : "memory")
#define CPA16(d, s)    asm volatile("cp.async.ca.shared.global [%0], [%1], 16;" :: "r"(d), "l"(s) : "memory")
#define CPWAITALL()    asm volatile("cp.async.wait_all;" ::: "memory")

__device__ __forceinline__ void ldm4(uint32_t* r, uint32_t addr) {
    asm volatile("ldmatrix.sync.aligned.m8n8.x4.shared.b16 {%0,%1,%2,%3}, [%4];"
                 : "=r"(r[0]), "=r"(r[1]), "=r"(r[2]), "=r"(r[3]) : "r"(addr));
}
__device__ __forceinline__ void mma_f16(float* c, const uint32_t* a, uint32_t b0, uint32_t b1) {
    asm volatile(
        "mma.sync.aligned.m16n8k16.row.col.f32.f16.f16.f32 "
        "{%0,%1,%2,%3}, {%4,%5,%6,%7}, {%8,%9}, {%0,%1,%2,%3};"
        : "+f"(c[0]), "+f"(c[1]), "+f"(c[2]), "+f"(c[3])
        : "r"(a[0]), "r"(a[1]), "r"(a[2]), "r"(a[3]), "r"(b0), "r"(b1));
}

// ---------------- prep: transpose + fp16 pack (blocks 0..383) + weight repack (rest) ----------------
__global__ void k_prep(const float* __restrict__ x,
                       const float* __restrict__ w_off, const float* __restrict__ w_dc) {
    if (blockIdx.x < BB * HH) {
        __shared__ float tile[64][97];
        int bh = blockIdx.x;
        int b = bh / HH;
        const float* src = x + ((size_t)b * CC) * HWIMG + (size_t)(bh % HH) * WW;
        for (int i = threadIdx.x; i < CC * WW; i += blockDim.x) {
            int c = i / WW, w = i % WW;
            tile[c][w] = src[(size_t)c * HWIMG + w];
        }
        __syncthreads();
        uint2* dst16 = g_xh16 + (size_t)bh * WW * 16;
        for (int i = threadIdx.x; i < WW * 16; i += blockDim.x) {
            int w = i >> 4, ck = i & 15;
            float c0 = tile[ck * 4 + 0][w], c1 = tile[ck * 4 + 1][w];
            float c2 = tile[ck * 4 + 2][w], c3 = tile[ck * 4 + 3][w];
            dst16[i] = make_uint2(pack_f16(c0, c1), pack_f16(c2, c3));
        }
    } else {
        int i = (blockIdx.x - BB * HH) * 256 + threadIdx.x;
        if (i < OO * CC * KK) {
            int o = i / (CC * KK);
            int r = i % (CC * KK);
            int c = r / KK;
            int k = r % KK;
            uint32_t sw = SWZ((uint32_t)(o * 128 + c * 2));
            __half* base = (__half*)g_wdc16;
            base[(size_t)k * 4096 + (sw >> 1)] = __float2half(w_dc[i]);
        }
        if (i < 32 * CC * KK) {
            int o = i / (CC * KK);
            int r = i % (CC * KK);
            int c = r / KK;
            int k = r % KK;
            float v = (o < TT) ? w_off[(size_t)o * CC * KK + c * KK + k] : 0.f;
            uint32_t sw = SWZ((uint32_t)(o * 128 + c * 2));
            __half* base = (__half*)g_woff16;
            base[(size_t)k * 2048 + (sw >> 1)] = __float2half(v);
        }
    }
}

// ============== fused offset-conv + deformable conv (all fp16) ==============
// smem: A 2x16KB = 32768 | W 2x8KB = 16384 | sP 8KB | sOffs 10240
#define MAIN_SW   32768
#define MAIN_SP   (MAIN_SW + 16384)
#define MAIN_SO   (MAIN_SP + 8192)
#define MAIN_SMEM (MAIN_SO + 10240)

__global__ void __launch_bounds__(256, 3) k_fused(const float* __restrict__ b_off,
                                                  const float* __restrict__ b_dc,
                                                  float* __restrict__ out) {
    extern __shared__ __align__(1024) char smem[];
    uint32_t sb = smem_u32(smem);
    float* sP = (float*)(smem + MAIN_SP);
    float* sOffs = (float*)(smem + MAIN_SO);   // [128][20] offsets, persists into phase B

    int tid = threadIdx.x;
    int wid = tid >> 5, lane = tid & 31;

    int pix0 = blockIdx.x * MT;
    int b = pix0 / HWIMG, ip0 = pix0 % HWIMG;
    const char* xh16 = (const char*)(g_xh16 + (size_t)b * HWIMG * 16);
    int lpx = tid >> 4;      // gather pixel sub-index
    int ck  = tid & 15;      // channel chunk (4 fp16 ch = 8B)

    int ph = 0, pw = 0;
    if (tid < 128) {
        int ip = ip0 + tid;
        ph = ip / WW; pw = ip - ph * WW;
    }

    uint32_t swbase;   // gather STS base (128B fp16 rows, 8B per chunk)
    {
        uint32_t chb = (uint32_t)(ck * 8);
        swbase = ((uint32_t)(lpx * 128) + chb) ^ ((uint32_t)(lpx & 7) << 4);
    }
    uint32_t lmask = (uint32_t)(lane & 7) << 4;

    // ===================== PHASE A: offset conv, fp16 (N=24 used of 32) =====================
    {
        int m0 = wid * 32;   // valid for wid<4
        uint32_t arowA[2], browo[2], segAo, segBo;
        {
            int rowoffA = ((lane >> 3) & 1) * 8 + (lane & 7);
            segAo = (uint32_t)((lane >> 4) * 16);
#pragma unroll
            for (int mt = 0; mt < 2; mt++)
                arowA[mt] = (uint32_t)((m0 + mt * 16 + rowoffA) * 128);
            int rowoffB = ((lane >> 4) & 1) * 8 + (lane & 7);
            segBo = (uint32_t)(((lane >> 3) & 1) * 16);
#pragma unroll
            for (int ntp = 0; ntp < 2; ntp++)
                browo[ntp] = (uint32_t)((ntp * 16 + rowoffB) * 128);
        }
        int t2 = tid - 128;
        int lpx2 = (t2 >> 4) & 7, ck2 = t2 & 15;
        uint32_t swb2 = ((uint32_t)(lpx2 * 128 + ck2 * 8)) ^ ((uint32_t)lpx2 << 4);

        float acc[2][3][4];
#pragma unroll
        for (int nt = 0; nt < 3; nt++) {
            int o = nt * 8 + (lane & 3) * 2;
            float b0v = (o < TT) ? b_off[o] : 0.f;
            float b1v = (o + 1 < TT) ? b_off[o + 1] : 0.f;
#pragma unroll
            for (int mt = 0; mt < 2; mt++) {
                acc[mt][nt][0] = b0v; acc[mt][nt][1] = b1v;
                acc[mt][nt][2] = b0v; acc[mt][nt][3] = b1v;
            }
        }

#define POFF(KI, PB) do {                                                          \
        int y = ph + (KI) / 3 - 1, x = pw + (KI) % 3 - 1;                          \
        int sz = ((unsigned)y < HH && (unsigned)x < WW) ? 8 : 0;                   \
        int yc = min(max(y, 0), HH - 1), xc = min(max(x, 0), WW - 1);              \
        int2* p = (int2*)(sP + (PB) * 256) + tid;                                  \
        *p = make_int2(sz, (yc * WW + xc) * 128);                                  \
    } while (0)

#define GATHS(BUF, PB) do {                                                        \
        uint32_t dh = sb + (BUF) * 16384 + swb2;                                   \
        const int2* sPp = (const int2*)(sP + (PB) * 256);                          \
        _Pragma("unroll")                                                          \
        for (int ps = 0; ps < 16; ps++) {                                          \
            int2 pv = sPp[ps * 8 + lpx2];                                          \
            const char* srcp = xh16 + pv.y + ck2 * 8;                              \
            CPA8(dh + ps * 1024, srcp, pv.x);                                      \
        }                                                                          \
    } while (0)

#define WCOPYO(KI, BUF) do {                                                       \
        const char* srcw = (const char*)(g_woff16 + (size_t)(KI) * 256);           \
        uint32_t dstw = sb + MAIN_SW + (BUF) * 4096;                               \
        for (int i = tid - 128; i < 256; i += 128) CPA16(dstw + i * 16, srcw + i * 16); \
    } while (0)

        if (tid < 128) POFF(0, 0);
        else           WCOPYO(0, 0);
        __syncthreads();
        if (tid >= 128) GATHS(0, 0);
        else            POFF(1, 1);
        CPWAITALL();
        __syncthreads();

#pragma unroll 1
        for (int k = 0; k < KK; k++) {
            int buf = k & 1;
            if (tid < 128) {
                if (k < KK - 2) POFF(k + 2, buf);
                uint32_t abF = sb + buf * 16384;
                uint32_t wbF = sb + MAIN_SW + buf * 4096;
#pragma unroll
                for (int kt = 0; kt < 4; kt++) {
                    uint32_t colA = ((uint32_t)(kt * 32) + segAo) ^ lmask;
                    uint32_t colB = ((uint32_t)(kt * 32) + segBo) ^ lmask;
                    uint32_t bF[2][4];
#pragma unroll
                    for (int ntp = 0; ntp < 2; ntp++)
                        ldm4(bF[ntp], wbF + browo[ntp] + colB);
#pragma unroll
                    for (int mt = 0; mt < 2; mt++) {
                        uint32_t aF[4];
                        ldm4(aF, abF + arowA[mt] + colA);
#pragma unroll
                        for (int nt = 0; nt < 3; nt++) {
                            int ntp = nt >> 1, hi2 = (nt & 1) * 2;
                            mma_f16(acc[mt][nt], aF, bF[ntp][hi2], bF[ntp][hi2 + 1]);
                        }
                    }
                }
            } else {
                if (k < KK - 1) {
                    WCOPYO(k + 1, buf ^ 1);
                    GATHS(buf ^ 1, (k + 1) & 1);
                }
            }
            CPWAITALL();
            __syncthreads();
        }

        // epilogue A: write offsets straight into persistent smem sOffs[p][20]
        if (tid < 128) {
#pragma unroll
            for (int mt = 0; mt < 2; mt++)
#pragma unroll
                for (int nt = 0; nt < 3; nt++) {
                    int o = nt * 8 + (lane & 3) * 2;
                    int p = m0 + mt * 16 + (lane >> 2);
                    if (o < TT) {
                        sOffs[p * 20 + o] = acc[mt][nt][0];
                        sOffs[(p + 8) * 20 + o] = acc[mt][nt][2];
                    }
                    if (o + 1 < TT) {
                        sOffs[p * 20 + o + 1] = acc[mt][nt][1];
                        sOffs[(p + 8) * 20 + o + 1] = acc[mt][nt][3];
                    }
                }
        }
#undef POFF
#undef GATHS
#undef WCOPYO
    }
    __syncthreads();   // sOffs visible; A/W smem free for phase B

    // ===================== PHASE B: main deformable conv, fp16 (N=64) =====================
    {
        int wm = wid & 3, wn = wid >> 2;
        int m0 = wm * 32, n0 = wn * 32;

        uint32_t arow[2], brow[2], segA, segB;
        {
            int rowoffA = ((lane >> 3) & 1) * 8 + (lane & 7);
            segA = (uint32_t)((lane >> 4) * 16);
#pragma unroll
            for (int mt = 0; mt < 2; mt++)
                arow[mt] = (uint32_t)((m0 + mt * 16 + rowoffA) * 128);
            int rowoffB = ((lane >> 4) & 1) * 8 + (lane & 7);
            segB = (uint32_t)(((lane >> 3) & 1) * 16);
#pragma unroll
            for (int ntp = 0; ntp < 2; ntp++)
                brow[ntp] = (uint32_t)((n0 + ntp * 16 + rowoffB) * 128);
        }

        float acc[2][4][4];
#pragma unroll
        for (int nt = 0; nt < 4; nt++) {
            int o = n0 + nt * 8 + (lane & 3) * 2;
            float b0v = b_dc[o], b1v = b_dc[o + 1];
#pragma unroll
            for (int mt = 0; mt < 2; mt++) {
                acc[mt][nt][0] = b0v; acc[mt][nt][1] = b1v;
                acc[mt][nt][2] = b0v; acc[mt][nt][3] = b1v;
            }
        }

// PARAMS: read offsets from smem; store half2-splatted weights + byte offsets
#define PARAMS(KI, PB) do {                                                        \
        float2 dxy = *(const float2*)(sOffs + tid * 20 + 2 * (KI));                \
        float py  = (float)(ph + (KI) / 3 - 1) + dxy.x;                            \
        float pxx = (float)(pw + (KI) % 3 - 1) + dxy.y;                            \
        float y0f = floorf(py), x0f = floorf(pxx);                                 \
        float ly = py - y0f, lx = pxx - x0f;                                       \
        int y0 = (int)y0f, x0 = (int)x0f, y1 = y0 + 1, x1 = x0 + 1;                \
        float w00 = (1.f - ly) * (1.f - lx), w01 = (1.f - ly) * lx;                \
        float w10 = ly * (1.f - lx), w11 = ly * lx;                                \
        bool vy0 = (unsigned)y0 < HH, vy1 = (unsigned)y1 < HH;                     \
        bool vx0 = (unsigned)x0 < WW, vx1 = (unsigned)x1 < WW;                     \
        w00 *= (float)(vy0 && vx0); w01 *= (float)(vy0 && vx1);                    \
        w10 *= (float)(vy1 && vx0); w11 *= (float)(vy1 && vx1);                    \
        int yc0 = min(max(y0, 0), HH - 1), yc1 = min(max(y1, 0), HH - 1);          \
        int xc0 = min(max(x0, 0), WW - 1), xc1 = min(max(x1, 0), WW - 1);          \
        uint4* p = (uint4*)(sP + (PB) * 1024) + tid * 2;                           \
        p[0] = make_uint4(splat_h2(w00), splat_h2(w01), splat_h2(w10), splat_h2(w11)); \
        p[1] = make_uint4((uint32_t)((yc0 * WW + xc0) * 128),                      \
                          (uint32_t)((yc0 * WW + xc1) * 128),                      \
                          (uint32_t)((yc1 * WW + xc0) * 128),                      \
                          (uint32_t)((yc1 * WW + xc1) * 128));                     \
    } while (0)

#define BILIN(wvu, iv, OUT0, OUT1) do {                                            \
        uint2 a2 = *(const uint2*)(xh16 + iv.x + ck * 8);                          \
        uint2 b2 = *(const uint2*)(xh16 + iv.y + ck * 8);                          \
        uint2 c2 = *(const uint2*)(xh16 + iv.z + ck * 8);                          \
        uint2 d2 = *(const uint2*)(xh16 + iv.w + ck * 8);                          \
        __half2 s0 = __hmul2(u2h(a2.x), u2h(wvu.x));                               \
        s0 = __hfma2(u2h(b2.x), u2h(wvu.y), s0);                                   \
        s0 = __hfma2(u2h(c2.x), u2h(wvu.z), s0);                                   \
        s0 = __hfma2(u2h(d2.x), u2h(wvu.w), s0);                                   \
        __half2 s1 = __hmul2(u2h(a2.y), u2h(wvu.x));                               \
        s1 = __hfma2(u2h(b2.y), u2h(wvu.y), s1);                                   \
        s1 = __hfma2(u2h(c2.y), u2h(wvu.z), s1);                                   \
        s1 = __hfma2(u2h(d2.y), u2h(wvu.w), s1);                                   \
        OUT0 = h2u(s0); OUT1 = h2u(s1);                                            \
    } while (0)

#define GATHER0() do {                                                             \
        uint32_t dh = sb + swbase;                                                 \
        const uint4* sPp = (const uint4*)sP;                                       \
        _Pragma("unroll")                                                          \
        for (int ps = 0; ps < 8; ps++) {                                           \
            const uint4* pp = sPp + (ps * 16 + lpx) * 2;                           \
            uint4 wvu = pp[0], iv = pp[1];                                         \
            uint32_t o0, o1;                                                       \
            BILIN(wvu, iv, o0, o1);                                                \
            STS64(dh + ps * 2048, o0, o1);                                         \
        }                                                                          \
    } while (0)

#define WCOPYW(KI, BUF) do {                                                       \
        const char* srcw = (const char*)(g_wdc16 + (size_t)(KI) * 512);            \
        uint32_t dstw = sb + MAIN_SW + (BUF) * 8192;                               \
        for (int i = tid - 128; i < 512; i += 128) CPA16(dstw + i * 16, srcw + i * 16); \
    } while (0)

        if (tid < 128) PARAMS(0, 0);
        else           WCOPYW(0, 0);
        __syncthreads();
        GATHER0();
        if (tid < 128) PARAMS(1, 1);
        CPWAITALL();
        __syncthreads();

#pragma unroll 1
        for (int k = 0; k < KK; k++) {
            int buf = k & 1;
            if (tid < 128) {
                if (k < KK - 2) PARAMS(k + 2, buf);
            } else {
                if (k < KK - 1) WCOPYW(k + 1, buf ^ 1);
            }
            uint32_t abF = sb + buf * 16384;
            uint32_t wbF = sb + MAIN_SW + buf * 8192;
            uint32_t dh = sb + (buf ^ 1) * 16384 + swbase;
            const uint4* sPp = (const uint4*)(sP + ((k + 1) & 1) * 1024);
            bool dog = (k < KK - 1);

            uint32_t bF[2][4];
#pragma unroll
            for (int sub = 0; sub < 8; sub++) {
                const int kt = sub >> 1, mt = sub & 1;
                uint4 wvu, iv;
                if (dog) {
                    const uint4* pp = sPp + (sub * 16 + lpx) * 2;
                    wvu = pp[0]; iv = pp[1];
                }
                uint32_t colA = ((uint32_t)(kt * 32) + segA) ^ lmask;
                uint32_t aF[4];
                ldm4(aF, abF + arow[mt] + colA);
                if (mt == 0) {
                    uint32_t colB = ((uint32_t)(kt * 32) + segB) ^ lmask;
                    ldm4(bF[0], wbF + brow[0] + colB);
                    ldm4(bF[1], wbF + brow[1] + colB);
                }
#pragma unroll
                for (int nt = 0; nt < 4; nt++) {
                    int ntp = nt >> 1, hi2 = (nt & 1) * 2;
                    mma_f16(acc[mt][nt], aF, bF[ntp][hi2], bF[ntp][hi2 + 1]);
                }
                if (dog) {
                    uint32_t o0, o1;
                    BILIN(wvu, iv, o0, o1);
                    STS64(dh + sub * 2048, o0, o1);
                }
            }
            CPWAITALL();
            __syncthreads();
        }

        // epilogue B: transpose via smem, coalesced NCHW float4 stores
        float* oT = (float*)smem;   // [64][132]
#pragma unroll
        for (int mt = 0; mt < 2; mt++)
#pragma unroll
            for (int nt = 0; nt < 4; nt++) {
                int o = n0 + nt * 8 + (lane & 3) * 2;
                int p = m0 + mt * 16 + (lane >> 2);
                oT[o * 132 + p]           = acc[mt][nt][0];
                oT[(o + 1) * 132 + p]     = acc[mt][nt][1];
                oT[o * 132 + p + 8]       = acc[mt][nt][2];
                oT[(o + 1) * 132 + p + 8] = acc[mt][nt][3];
            }
        __syncthreads();
        {
            size_t obase = (size_t)b * OO * HWIMG + ip0;
            for (int i = tid; i < OO * (MT / 4); i += 256) {
                int o = i >> 5, p4 = i & 31;
                float4 v = *(const float4*)(oT + o * 132 + p4 * 4);
                *(float4*)(out + obase + (size_t)o * HWIMG + p4 * 4) = v;
            }
        }
#undef PARAMS
#undef BILIN
#undef GATHER0
#undef WCOPYW
    }
}

// ---------------- launch ----------------
extern "C" void kernel_launch(void* const* d_in, const int* in_sizes, int n_in,
                              void* d_out, int out_size) {
    const float* x     = (const float*)d_in[0];
    const float* w_off = (const float*)d_in[1];
    const float* b_off = (const float*)d_in[2];
    const float* w_dc  = (const float*)d_in[3];
    const float* b_dc  = (const float*)d_in[4];
    float* out = (float*)d_out;

    cudaFuncSetAttribute(k_fused, cudaFuncAttributeMaxDynamicSharedMemorySize, MAIN_SMEM);

    k_prep<<<BB * HH + (OO * CC * KK + 255) / 256, 256>>>(x, w_off, w_dc);
    k_fused<<<NTIL, 256, MAIN_SMEM>>>(b_off, b_dc, out);
}